// round 15
// baseline (speedup 1.0000x reference)
#include <cuda_runtime.h>
#include <cstdint>

#define BATCH 256
#define SEQ   197
#define DIMC  768
#define HEADS 12
#define HD    64
#define MTOT  (BATCH*SEQ)      /* 50432 */
#define QSCALE 0.125f

// ---------------- scratch (static device globals; no allocation) ----------------
// NOTE: g_X, g_W1, g_W2, g_Q, g_K, g_ATT are stored with a k-dimension permutation:
// within every 8-float group along the contraction dim, order is [k0,k4,k1,k5,k2,k6,k3,k7],
// so an MMA thread's (c, c+4) fragment pair is CONTIGUOUS -> float2 LDS.
__device__ __align__(16) float g_X [(size_t)MTOT*DIMC];
__device__ __align__(16) float g_W1[3*DIMC*DIMC];
__device__ __align__(16) float g_W2[DIMC*DIMC];
__device__ __align__(16) float g_Q[BATCH*HEADS*SEQ*HD];   // hd-permuted
__device__ __align__(16) float g_K[BATCH*HEADS*SEQ*HD];   // hd-permuted
__device__ __align__(16) float g_V[BATCH*HEADS*SEQ*HD];   // NOT permuted
__device__ __align__(16) float g_ATT[(size_t)MTOT*DIMC];  // channel-permuted
__device__ __align__(16) float g_BIAS[HEADS*SEQ*SEQ];

// ---------------- helpers ----------------
__device__ __forceinline__ float to_tf32(float x){
    float r; asm("cvt.rna.tf32.f32 %0, %1;" : "=f"(r) : "f"(x)); return r;
}
__device__ __forceinline__ void cp16(void* s, const void* g){
    unsigned saddr = (unsigned)__cvta_generic_to_shared(s);
    asm volatile("cp.async.cg.shared.global [%0], [%1], 16;\n" :: "r"(saddr), "l"(g));
}
__device__ __forceinline__ void mma8(float* c, const uint32_t* a, const uint32_t* b){
    asm volatile("mma.sync.aligned.m16n8k8.row.col.f32.tf32.tf32.f32 "
        "{%0,%1,%2,%3}, {%4,%5,%6,%7}, {%8,%9}, {%0,%1,%2,%3};"
        : "+f"(c[0]),"+f"(c[1]),"+f"(c[2]),"+f"(c[3])
        : "r"(a[0]),"r"(a[1]),"r"(a[2]),"r"(a[3]),"r"(b[0]),"r"(b[1]));
}
__device__ __forceinline__ uint32_t fbits(float x){ return __float_as_uint(x); }
// physical position of logical index `col` under the 8-group permutation
__device__ __forceinline__ int perm8(int col){
    int j = col & 7;
    int pj = (j < 4) ? (2*j) : (2*(j-4)+1);
    return (col & ~7) | pj;
}

// ---------------- prep: tf32-round + k-permute, 8 floats per thread ----------------
template<int DST>
__global__ void round_perm_kernel(const float* __restrict__ src, int n8){
    int i = blockIdx.x*256 + threadIdx.x;
    if (i >= n8) return;
    const float4* s4 = reinterpret_cast<const float4*>(src);
    float4 v0 = s4[2*i], v1 = s4[2*i+1];
    v0.x=to_tf32(v0.x); v0.y=to_tf32(v0.y); v0.z=to_tf32(v0.z); v0.w=to_tf32(v0.w);
    v1.x=to_tf32(v1.x); v1.y=to_tf32(v1.y); v1.z=to_tf32(v1.z); v1.w=to_tf32(v1.w);
    float4 o0 = make_float4(v0.x, v1.x, v0.y, v1.y);   // k0,k4,k1,k5
    float4 o1 = make_float4(v0.z, v1.z, v0.w, v1.w);   // k2,k6,k3,k7
    float* dst = (DST==0) ? g_X : (DST==1) ? g_W1 : g_W2;
    reinterpret_cast<float4*>(dst)[2*i]   = o0;
    reinterpret_cast<float4*>(dst)[2*i+1] = o1;
}

// ---------------- bias gather ----------------
__global__ void bias_gather_kernel(const float* __restrict__ table,
                                   const int* __restrict__ rel_index){
    int idx = blockIdx.x * 256 + threadIdx.x;
    const int tot = HEADS*SEQ*SEQ;
    if (idx >= tot) return;
    int h  = idx / (SEQ*SEQ);
    int ij = idx - h*(SEQ*SEQ);
    g_BIAS[idx] = table[rel_index[ij]*HEADS + h];
}

// ---------------- TF32 GEMM: block 256x128, warp 64x64, k-tile 32 ----------------
// MODE 0: A=g_X, W=g_W1 -> g_Q (scale+bias, hd-perm), g_K (hd-perm), g_V (plain)
// MODE 1: A=g_ATT, W=g_W2 -> Out + proj_b (plain)
#define SMA  40              /* smem row stride: 8-bank stagger -> LDS.64 conflict-free */
#define ABUF (256*SMA)       /* 10240 floats per A buffer */
#define BBUF (128*SMA)       /* 5120 floats per B buffer */
template<int MODE>
__global__ void __launch_bounds__(256,1) gemm_tf32(
    const float* __restrict__ bias_a, const float* __restrict__ bias_b,
    float* __restrict__ Out)
{
    const int K = DIMC;
    extern __shared__ float sm[];
    float* As = sm;               // 2 * ABUF
    float* Bs = sm + 2*ABUF;      // 2 * BBUF
    const int tid = threadIdx.x;
    const int m0 = blockIdx.y * 256;
    const int n0 = blockIdx.x * 128;
    const float* Ap = (MODE == 0) ? g_X  : g_ATT;
    const float* Wp = (MODE == 0) ? g_W1 : g_W2;

    float acc[4][8][4];
    #pragma unroll
    for (int i=0;i<4;i++)
        #pragma unroll
        for (int j=0;j<8;j++)
            #pragma unroll
            for (int r=0;r<4;r++) acc[i][j][r]=0.f;

    const int NT = K/32;  // 24
    auto load_tile = [&](int kt, int buf){
        const int k0 = kt*32;
        #pragma unroll
        for (int i=0;i<8;i++){
            int idx = tid + i*256;               // 0..2047
            int row = idx >> 3, c4 = (idx & 7)*4;
            cp16(&As[buf*ABUF + row*SMA + c4], &Ap[(size_t)(m0+row)*K + k0 + c4]);
        }
        #pragma unroll
        for (int i=0;i<4;i++){
            int idx = tid + i*256;               // 0..1023
            int row = idx >> 3, c4 = (idx & 7)*4;
            cp16(&Bs[buf*BBUF + row*SMA + c4], &Wp[(size_t)(n0+row)*K + k0 + c4]);
        }
        asm volatile("cp.async.commit_group;");
    };
    load_tile(0, 0);

    const int wid = tid>>5, lane = tid&31;
    const int wm = (wid&3)*64, wn = (wid>>2)*64;
    const int lr = lane>>2, lc = lane&3;

    for (int kt=0; kt<NT; kt++){
        const int buf = kt & 1;
        asm volatile("cp.async.wait_group 0;");
        __syncthreads();                        // tile visible; prev reads of buf^1 done
        if (kt+1 < NT) load_tile(kt+1, buf^1);  // overlaps MMA below
        const float* As_ = &As[buf*ABUF];
        const float* Bs_ = &Bs[buf*BBUF];
        #pragma unroll
        for (int kk=0; kk<4; kk++){
            const int c2 = kk*8 + 2*lc;         // physical: logical pair (c, c+4)
            float2 af[4][2];
            #pragma unroll
            for (int mi=0; mi<4; mi++){
                int r = wm + mi*16 + lr;
                af[mi][0] = *reinterpret_cast<const float2*>(&As_[r*SMA + c2]);
                af[mi][1] = *reinterpret_cast<const float2*>(&As_[(r+8)*SMA + c2]);
            }
            #pragma unroll
            for (int ni=0; ni<8; ni++){
                int n = wn + ni*8 + lr;
                float2 bf = *reinterpret_cast<const float2*>(&Bs_[n*SMA + c2]);
                uint32_t bv[2] = { fbits(bf.x), fbits(bf.y) };
                #pragma unroll
                for (int mi=0;mi<4;mi++){
                    uint32_t av[4] = { fbits(af[mi][0].x), fbits(af[mi][1].x),
                                       fbits(af[mi][0].y), fbits(af[mi][1].y) };
                    mma8(acc[mi][ni], av, bv);
                }
            }
        }
    }
    __syncthreads();

    // ---------------- epilogue ----------------
    if constexpr (MODE == 0){
        const int sec = n0 / DIMC;  // 0=Q, 1=K, 2=V (128 | 768: block stays in one section)
        #pragma unroll
        for (int mi=0; mi<4; mi++){
            #pragma unroll
            for (int rh=0; rh<2; rh++){
                int m = m0 + wm + mi*16 + rh*8 + lr;
                int bb = m / SEQ;
                int t  = m - bb*SEQ;
                #pragma unroll
                for (int ni=0; ni<8; ni++){
                    #pragma unroll
                    for (int cp=0; cp<2; cp++){
                        int n = n0 + wn + ni*8 + lc*2 + cp;
                        int d = n - sec*DIMC;
                        int h = d >> 6, hdc = d & 63;
                        float v = acc[mi][ni][rh*2 + cp];
                        int rowbase = ((bb*HEADS + h)*SEQ + t)*HD;
                        if (sec == 0)      g_Q[rowbase + perm8(hdc)] = to_tf32((v + bias_a[d]) * QSCALE);
                        else if (sec == 1) g_K[rowbase + perm8(hdc)] = to_tf32(v);
                        else               g_V[rowbase + hdc]        = to_tf32(v + bias_b[d]);
                    }
                }
            }
        }
    } else {
        #pragma unroll
        for (int mi=0; mi<4; mi++){
            #pragma unroll
            for (int rh=0; rh<2; rh++){
                int m = m0 + wm + mi*16 + rh*8 + lr;
                #pragma unroll
                for (int ni=0; ni<8; ni++){
                    int n = n0 + wn + ni*8 + lc*2;
                    float2 o;
                    o.x = acc[mi][ni][rh*2 + 0] + bias_a[n];
                    o.y = acc[mi][ni][rh*2 + 1] + bias_a[n+1];
                    *reinterpret_cast<float2*>(&Out[(size_t)m*DIMC + n]) = o;
                }
            }
        }
    }
}

// ---------------- attention: one block per (b, h); loops 4 q-tiles ----------------
#define NK 208
#define LQ 72                /* 8-bank stagger: conflict-free LDS.64 + V LDS.32 */
#define LP 216
__global__ void __launch_bounds__(256) attn_kernel(){
    extern __shared__ float sm[];
    float* Qs = sm;                   // 64  * 72  (hd-permuted, from g_Q)
    float* Ks = Qs + 64*LQ;           // 208 * 72  (hd-permuted, from g_K)
    float* Vs = Ks + NK*LQ;           // 208 * 72  (plain)
    float* Ps = Vs + NK*LQ;           // 64  * 216 (key-permuted columns)

    const int tid = threadIdx.x;
    const int h = blockIdx.x, b = blockIdx.y;
    const size_t base = (size_t)(b*HEADS + h)*SEQ*HD;

    // load K and V once (zero-pad rows past 197)
    #pragma unroll
    for (int i=0;i<13;i++){
        int idx = tid + i*256;                 // 0..3327
        int row = idx >> 4, c4 = (idx & 15)*4;
        float4 v = make_float4(0.f,0.f,0.f,0.f);
        if (row < SEQ) v = *reinterpret_cast<const float4*>(&g_K[base + (size_t)row*HD + c4]);
        *reinterpret_cast<float4*>(&Ks[row*LQ + c4]) = v;
        v = make_float4(0.f,0.f,0.f,0.f);
        if (row < SEQ) v = *reinterpret_cast<const float4*>(&g_V[base + (size_t)row*HD + c4]);
        *reinterpret_cast<float4*>(&Vs[row*LQ + c4]) = v;
    }
    __syncthreads();

    const int wid = tid>>5, lane = tid&31, lr = lane>>2, lc = lane&3;

    for (int qt=0; qt<4; qt++){
        #pragma unroll
        for (int i=0;i<4;i++){
            int idx = tid + i*256;
            int row = idx >> 4, c4 = (idx & 15)*4;
            int q = qt*64 + row;
            float4 v = make_float4(0.f,0.f,0.f,0.f);
            if (q < SEQ) v = *reinterpret_cast<const float4*>(&g_Q[base + (size_t)q*HD + c4]);
            *reinterpret_cast<float4*>(&Qs[row*LQ + c4]) = v;
        }
        __syncthreads();

        // -------- phase 1: S = Q K^T, 8 warps 4(m) x 2(n), warp tile 16 x 104 --------
        {
            const int wm = (wid&3)*16, wn = (wid>>2)*104;
            float acc[13][4];
            #pragma unroll
            for (int ni=0;ni<13;ni++)
                #pragma unroll
                for (int r=0;r<4;r++) acc[ni][r]=0.f;
            #pragma unroll
            for (int kk=0; kk<8; kk++){
                const int c2 = kk*8 + 2*lc;
                int r = wm + lr;
                float2 a0 = *reinterpret_cast<const float2*>(&Qs[r*LQ + c2]);
                float2 a1 = *reinterpret_cast<const float2*>(&Qs[(r+8)*LQ + c2]);
                uint32_t av[4] = { fbits(a0.x), fbits(a1.x), fbits(a0.y), fbits(a1.y) };
                #pragma unroll
                for (int ni=0; ni<13; ni++){
                    int n = wn + ni*8 + lr;
                    float2 bf = *reinterpret_cast<const float2*>(&Ks[n*LQ + c2]);
                    uint32_t bv[2] = { fbits(bf.x), fbits(bf.y) };
                    mma8(acc[ni], av, bv);
                }
            }
            // S + bias -> Ps at PERMUTED key column (masked -> -1e30)
            #pragma unroll
            for (int ni=0; ni<13; ni++){
                #pragma unroll
                for (int r=0;r<4;r++){
                    int row = wm + (r>>1)*8 + lr;
                    int j   = wn + ni*8 + lc*2 + (r&1);
                    int qg  = qt*64 + row;
                    float v;
                    if (j >= SEQ) v = -1e30f;
                    else if (qg < SEQ) v = acc[ni][r] + g_BIAS[(h*SEQ + qg)*SEQ + j];
                    else v = 0.f;
                    Ps[row*LP + perm8(j)] = v;
                }
            }
        }
        __syncthreads();

        // -------- softmax (row reduction; column order irrelevant) --------
        #pragma unroll
        for (int rr=0; rr<8; rr++){
            int row = (tid>>5) + rr*8;
            float* prow = &Ps[row*LP];
            float vals[7];
            float mx = -1e30f;
            #pragma unroll
            for (int i=0;i<7;i++){
                int j = lane + i*32;
                vals[i] = (j < NK) ? prow[j] : -1e30f;
                mx = fmaxf(mx, vals[i]);
            }
            #pragma unroll
            for (int o=16;o>0;o>>=1) mx = fmaxf(mx, __shfl_xor_sync(0xffffffffu, mx, o));
            float s = 0.f;
            #pragma unroll
            for (int i=0;i<7;i++){ vals[i] = __expf(vals[i]-mx); s += vals[i]; }
            #pragma unroll
            for (int o=16;o>0;o>>=1) s += __shfl_xor_sync(0xffffffffu, s, o);
            float inv = 1.f / s;
            #pragma unroll
            for (int i=0;i<7;i++){
                int j = lane + i*32;
                if (j < NK) prow[j] = to_tf32(vals[i]*inv);
            }
        }
        __syncthreads();

        // -------- phase 2: O = P V, warp tile 16 x 32, K = 208 --------
        {
            const int wm = (wid&3)*16, wn = (wid>>2)*32;
            float acc[4][4];
            #pragma unroll
            for (int ni=0;ni<4;ni++)
                #pragma unroll
                for (int r=0;r<4;r++) acc[ni][r]=0.f;
            #pragma unroll
            for (int ks=0; ks<26; ks++){
                const int c2 = ks*8 + 2*lc;        // permuted P columns
                const int cl = ks*8 + lc;          // logical V rows
                int r = wm + lr;
                float2 a0 = *reinterpret_cast<const float2*>(&Ps[r*LP + c2]);
                float2 a1 = *reinterpret_cast<const float2*>(&Ps[(r+8)*LP + c2]);
                uint32_t av[4] = { fbits(a0.x), fbits(a1.x), fbits(a0.y), fbits(a1.y) };
                #pragma unroll
                for (int ni=0;ni<4;ni++){
                    int n = wn + ni*8 + lr;
                    uint32_t bv[2];
                    bv[0] = fbits(Vs[cl*LQ + n]);
                    bv[1] = fbits(Vs[(cl+4)*LQ + n]);
                    mma8(acc[ni], av, bv);
                }
            }
            #pragma unroll
            for (int ni=0;ni<4;ni++){
                #pragma unroll
                for (int r=0;r<4;r++){
                    int row = wm + (r>>1)*8 + lr;
                    int hdc = wn + ni*8 + lc*2 + (r&1);
                    int qg  = qt*64 + row;
                    if (qg < SEQ)
                        g_ATT[((size_t)b*SEQ + qg)*DIMC + h*HD + perm8(hdc)] = to_tf32(acc[ni][r]);
                }
            }
        }
        __syncthreads();   // before next q-tile overwrites Qs/Ps
    }
}

// ---------------- launch ----------------
extern "C" void kernel_launch(void* const* d_in, const int* in_sizes, int n_in,
                              void* d_out, int out_size){
    const float* x      = (const float*)d_in[0];
    const float* qkv_w  = (const float*)d_in[1];
    const float* q_bias = (const float*)d_in[2];
    const float* v_bias = (const float*)d_in[3];
    const float* table  = (const float*)d_in[4];
    const float* proj_w = (const float*)d_in[5];
    const float* proj_b = (const float*)d_in[6];
    const int*   relidx = (const int*)d_in[7];
    float* out = (float*)d_out;

    const int gemm_smem = (2*ABUF + 2*BBUF) * (int)sizeof(float);           // 122880
    const int attn_smem = (64*LQ + 2*NK*LQ + 64*LP) * (int)sizeof(float);   // 193536
    cudaFuncSetAttribute(gemm_tf32<0>, cudaFuncAttributeMaxDynamicSharedMemorySize, gemm_smem);
    cudaFuncSetAttribute(gemm_tf32<1>, cudaFuncAttributeMaxDynamicSharedMemorySize, gemm_smem);
    cudaFuncSetAttribute(attn_kernel,  cudaFuncAttributeMaxDynamicSharedMemorySize, attn_smem);

    const int nx8  = (MTOT*DIMC)/8;           // 4,841,472
    const int nw18 = (3*DIMC*DIMC)/8;         // 221,184
    const int nw28 = (DIMC*DIMC)/8;           // 73,728
    round_perm_kernel<0><<<(nx8 +255)/256, 256>>>(x,      nx8);
    round_perm_kernel<1><<<(nw18+255)/256, 256>>>(qkv_w,  nw18);
    round_perm_kernel<2><<<(nw28+255)/256, 256>>>(proj_w, nw28);
    bias_gather_kernel<<<(HEADS*SEQ*SEQ + 255)/256, 256>>>(table, relidx);

    gemm_tf32<0><<<dim3(3*DIMC/128, MTOT/256), 256, gemm_smem>>>(
        q_bias, v_bias, nullptr);

    attn_kernel<<<dim3(HEADS, BATCH), 256, attn_smem>>>();

    gemm_tf32<1><<<dim3(DIMC/128, MTOT/256), 256, gemm_smem>>>(
        proj_b, nullptr, out);
}

// round 16
// speedup vs baseline: 1.1073x; 1.1073x over previous
#include <cuda_runtime.h>
#include <cstdint>

#define BATCH 256
#define SEQ   197
#define DIMC  768
#define HEADS 12
#define HD    64
#define MTOT  (BATCH*SEQ)      /* 50432 */
#define QSCALE 0.125f

// ---------------- scratch (static device globals; no allocation) ----------------
// g_X, g_W1, g_W2, g_Q, g_K, g_ATT use a k-dim permutation: within every 8-float
// group along the contraction dim, order is [k0,k4,k1,k5,k2,k6,k3,k7], so an MMA
// thread's (c, c+4) fragment pair is CONTIGUOUS -> one LDS.64 instead of two LDS.32.
__device__ __align__(16) float g_X [(size_t)MTOT*DIMC];
__device__ __align__(16) float g_W1[3*DIMC*DIMC];
__device__ __align__(16) float g_W2[DIMC*DIMC];
__device__ __align__(16) float g_Q[BATCH*HEADS*SEQ*HD];   // hd-permuted
__device__ __align__(16) float g_K[BATCH*HEADS*SEQ*HD];   // hd-permuted
__device__ __align__(16) float g_V[BATCH*HEADS*SEQ*HD];   // NOT permuted
__device__ __align__(16) float g_ATT[(size_t)MTOT*DIMC];  // channel-permuted
__device__ __align__(16) float g_BIAS[HEADS*SEQ*SEQ];

// ---------------- helpers ----------------
__device__ __forceinline__ float to_tf32(float x){
    float r; asm("cvt.rna.tf32.f32 %0, %1;" : "=f"(r) : "f"(x)); return r;
}
__device__ __forceinline__ void cp16(void* s, const void* g){
    unsigned saddr = (unsigned)__cvta_generic_to_shared(s);
    asm volatile("cp.async.cg.shared.global [%0], [%1], 16;\n" :: "r"(saddr), "l"(g));
}
__device__ __forceinline__ void mma8(float* c, const uint32_t* a, const uint32_t* b){
    asm volatile("mma.sync.aligned.m16n8k8.row.col.f32.tf32.tf32.f32 "
        "{%0,%1,%2,%3}, {%4,%5,%6,%7}, {%8,%9}, {%0,%1,%2,%3};"
        : "+f"(c[0]),"+f"(c[1]),"+f"(c[2]),"+f"(c[3])
        : "r"(a[0]),"r"(a[1]),"r"(a[2]),"r"(a[3]),"r"(b[0]),"r"(b[1]));
}
__device__ __forceinline__ uint32_t fbits(float x){ return __float_as_uint(x); }
__device__ __forceinline__ int perm8(int col){
    int j = col & 7;
    int pj = (j < 4) ? (2*j) : (2*(j-4)+1);
    return (col & ~7) | pj;
}

// ---------------- prep: tf32-round + k-permute, 8 floats per thread ----------------
template<int DST>
__global__ void round_perm_kernel(const float* __restrict__ src, int n8){
    int i = blockIdx.x*256 + threadIdx.x;
    if (i >= n8) return;
    const float4* s4 = reinterpret_cast<const float4*>(src);
    float4 v0 = s4[2*i], v1 = s4[2*i+1];
    v0.x=to_tf32(v0.x); v0.y=to_tf32(v0.y); v0.z=to_tf32(v0.z); v0.w=to_tf32(v0.w);
    v1.x=to_tf32(v1.x); v1.y=to_tf32(v1.y); v1.z=to_tf32(v1.z); v1.w=to_tf32(v1.w);
    float4 o0 = make_float4(v0.x, v1.x, v0.y, v1.y);   // k0,k4,k1,k5
    float4 o1 = make_float4(v0.z, v1.z, v0.w, v1.w);   // k2,k6,k3,k7
    float* dst = (DST==0) ? g_X : (DST==1) ? g_W1 : g_W2;
    reinterpret_cast<float4*>(dst)[2*i]   = o0;
    reinterpret_cast<float4*>(dst)[2*i+1] = o1;
}

// ---------------- bias gather ----------------
__global__ void bias_gather_kernel(const float* __restrict__ table,
                                   const int* __restrict__ rel_index){
    int idx = blockIdx.x * 256 + threadIdx.x;
    const int tot = HEADS*SEQ*SEQ;
    if (idx >= tot) return;
    int h  = idx / (SEQ*SEQ);
    int ij = idx - h*(SEQ*SEQ);
    g_BIAS[idx] = table[rel_index[ij]*HEADS + h];
}

// ---------------- TF32 GEMM: block 128x128, warp 32x64, k-tile 32, 2 CTAs/SM ----------------
// MODE 0: A=g_X, W=g_W1 -> g_Q (scale+bias, hd-perm), g_K (hd-perm), g_V (plain)
// MODE 1: A=g_ATT, W=g_W2 -> Out + proj_b (plain)
#define SMA  40              /* 8-bank stagger: LDS.64 fragment loads conflict-free */
#define TBUF (128*SMA)       /* 5120 floats per buffer */
template<int MODE>
__global__ void __launch_bounds__(256,2) gemm_tf32(
    const float* __restrict__ bias_a, const float* __restrict__ bias_b,
    float* __restrict__ Out)
{
    const int K = DIMC;
    extern __shared__ float sm[];
    float* As = sm;               // 2 * TBUF
    float* Bs = sm + 2*TBUF;      // 2 * TBUF
    const int tid = threadIdx.x;
    const int m0 = blockIdx.y * 128;
    const int n0 = blockIdx.x * 128;
    const float* Ap = (MODE == 0) ? g_X  : g_ATT;
    const float* Wp = (MODE == 0) ? g_W1 : g_W2;

    float acc[2][8][4];
    #pragma unroll
    for (int i=0;i<2;i++)
        #pragma unroll
        for (int j=0;j<8;j++)
            #pragma unroll
            for (int r=0;r<4;r++) acc[i][j][r]=0.f;

    const int NT = K/32;  // 24
    auto load_tile = [&](int kt, int buf){
        const int k0 = kt*32;
        #pragma unroll
        for (int i=0;i<4;i++){
            int idx = tid + i*256;               // 0..1023
            int row = idx >> 3, c4 = (idx & 7)*4;
            cp16(&As[buf*TBUF + row*SMA + c4], &Ap[(size_t)(m0+row)*K + k0 + c4]);
        }
        #pragma unroll
        for (int i=0;i<4;i++){
            int idx = tid + i*256;
            int row = idx >> 3, c4 = (idx & 7)*4;
            cp16(&Bs[buf*TBUF + row*SMA + c4], &Wp[(size_t)(n0+row)*K + k0 + c4]);
        }
        asm volatile("cp.async.commit_group;");
    };
    load_tile(0, 0);

    const int wid = tid>>5, lane = tid&31;
    const int wm = (wid&3)*32, wn = (wid>>2)*64;
    const int lr = lane>>2, lc = lane&3;

    for (int kt=0; kt<NT; kt++){
        const int buf = kt & 1;
        asm volatile("cp.async.wait_group 0;");
        __syncthreads();                        // tile kt visible; all reads of buf^1 done
        if (kt+1 < NT) load_tile(kt+1, buf^1);  // overlaps MMA below
        const float* As_ = &As[buf*TBUF];
        const float* Bs_ = &Bs[buf*TBUF];
        #pragma unroll
        for (int kk=0; kk<4; kk++){
            const int c2 = kk*8 + 2*lc;         // physical pos of logical pair (c, c+4)
            float2 af[2][2];
            #pragma unroll
            for (int mi=0; mi<2; mi++){
                int r = wm + mi*16 + lr;
                af[mi][0] = *reinterpret_cast<const float2*>(&As_[r*SMA + c2]);
                af[mi][1] = *reinterpret_cast<const float2*>(&As_[(r+8)*SMA + c2]);
            }
            #pragma unroll
            for (int ni=0; ni<8; ni++){
                int n = wn + ni*8 + lr;
                float2 bf = *reinterpret_cast<const float2*>(&Bs_[n*SMA + c2]);
                uint32_t bv[2] = { fbits(bf.x), fbits(bf.y) };
                #pragma unroll
                for (int mi=0;mi<2;mi++){
                    uint32_t av[4] = { fbits(af[mi][0].x), fbits(af[mi][1].x),
                                       fbits(af[mi][0].y), fbits(af[mi][1].y) };
                    mma8(acc[mi][ni], av, bv);
                }
            }
        }
    }
    __syncthreads();

    // ---------------- epilogue ----------------
    if constexpr (MODE == 0){
        const int sec = n0 / DIMC;  // 0=Q, 1=K, 2=V (128 | 768: block stays in one section)
        #pragma unroll
        for (int mi=0; mi<2; mi++){
            #pragma unroll
            for (int rh=0; rh<2; rh++){
                int m = m0 + wm + mi*16 + rh*8 + lr;
                int bb = m / SEQ;
                int t  = m - bb*SEQ;
                #pragma unroll
                for (int ni=0; ni<8; ni++){
                    #pragma unroll
                    for (int cp=0; cp<2; cp++){
                        int n = n0 + wn + ni*8 + lc*2 + cp;
                        int d = n - sec*DIMC;
                        int h = d >> 6, hdc = d & 63;
                        float v = acc[mi][ni][rh*2 + cp];
                        int rowbase = ((bb*HEADS + h)*SEQ + t)*HD;
                        if (sec == 0)      g_Q[rowbase + perm8(hdc)] = to_tf32((v + bias_a[d]) * QSCALE);
                        else if (sec == 1) g_K[rowbase + perm8(hdc)] = to_tf32(v);
                        else               g_V[rowbase + hdc]        = to_tf32(v + bias_b[d]);
                    }
                }
            }
        }
    } else {
        #pragma unroll
        for (int mi=0; mi<2; mi++){
            #pragma unroll
            for (int rh=0; rh<2; rh++){
                int m = m0 + wm + mi*16 + rh*8 + lr;
                #pragma unroll
                for (int ni=0; ni<8; ni++){
                    int n = n0 + wn + ni*8 + lc*2;
                    float2 o;
                    o.x = acc[mi][ni][rh*2 + 0] + bias_a[n];
                    o.y = acc[mi][ni][rh*2 + 1] + bias_a[n+1];
                    *reinterpret_cast<float2*>(&Out[(size_t)m*DIMC + n]) = o;
                }
            }
        }
    }
}

// ---------------- attention: one block per (b, h); loops 4 q-tiles ----------------
#define NK 208
#define LQ 72                /* 8-bank stagger: conflict-free LDS.64 + V LDS.32 */
#define LP 216
__global__ void __launch_bounds__(256) attn_kernel(){
    extern __shared__ float sm[];
    float* Qs = sm;                   // 64  * 72  (hd-permuted, from g_Q)
    float* Ks = Qs + 64*LQ;           // 208 * 72  (hd-permuted, from g_K)
    float* Vs = Ks + NK*LQ;           // 208 * 72  (plain)
    float* Ps = Vs + NK*LQ;           // 64  * 216 (key-permuted columns)

    const int tid = threadIdx.x;
    const int h = blockIdx.x, b = blockIdx.y;
    const size_t base = (size_t)(b*HEADS + h)*SEQ*HD;

    // load K and V once (zero-pad rows past 197)
    #pragma unroll
    for (int i=0;i<13;i++){
        int idx = tid + i*256;                 // 0..3327
        int row = idx >> 4, c4 = (idx & 15)*4;
        float4 v = make_float4(0.f,0.f,0.f,0.f);
        if (row < SEQ) v = *reinterpret_cast<const float4*>(&g_K[base + (size_t)row*HD + c4]);
        *reinterpret_cast<float4*>(&Ks[row*LQ + c4]) = v;
        v = make_float4(0.f,0.f,0.f,0.f);
        if (row < SEQ) v = *reinterpret_cast<const float4*>(&g_V[base + (size_t)row*HD + c4]);
        *reinterpret_cast<float4*>(&Vs[row*LQ + c4]) = v;
    }
    __syncthreads();

    const int wid = tid>>5, lane = tid&31, lr = lane>>2, lc = lane&3;

    for (int qt=0; qt<4; qt++){
        #pragma unroll
        for (int i=0;i<4;i++){
            int idx = tid + i*256;
            int row = idx >> 4, c4 = (idx & 15)*4;
            int q = qt*64 + row;
            float4 v = make_float4(0.f,0.f,0.f,0.f);
            if (q < SEQ) v = *reinterpret_cast<const float4*>(&g_Q[base + (size_t)q*HD + c4]);
            *reinterpret_cast<float4*>(&Qs[row*LQ + c4]) = v;
        }
        __syncthreads();

        // -------- phase 1: S = Q K^T, 8 warps 4(m) x 2(n), warp tile 16 x 104 --------
        {
            const int wm = (wid&3)*16, wn = (wid>>2)*104;
            float acc[13][4];
            #pragma unroll
            for (int ni=0;ni<13;ni++)
                #pragma unroll
                for (int r=0;r<4;r++) acc[ni][r]=0.f;
            #pragma unroll
            for (int kk=0; kk<8; kk++){
                const int c2 = kk*8 + 2*lc;
                int r = wm + lr;
                float2 a0 = *reinterpret_cast<const float2*>(&Qs[r*LQ + c2]);
                float2 a1 = *reinterpret_cast<const float2*>(&Qs[(r+8)*LQ + c2]);
                uint32_t av[4] = { fbits(a0.x), fbits(a1.x), fbits(a0.y), fbits(a1.y) };
                #pragma unroll
                for (int ni=0; ni<13; ni++){
                    int n = wn + ni*8 + lr;
                    float2 bf = *reinterpret_cast<const float2*>(&Ks[n*LQ + c2]);
                    uint32_t bv[2] = { fbits(bf.x), fbits(bf.y) };
                    mma8(acc[ni], av, bv);
                }
            }
            // S + bias -> Ps at PERMUTED key column (masked -> -1e30)
            #pragma unroll
            for (int ni=0; ni<13; ni++){
                #pragma unroll
                for (int r=0;r<4;r++){
                    int row = wm + (r>>1)*8 + lr;
                    int j   = wn + ni*8 + lc*2 + (r&1);
                    int qg  = qt*64 + row;
                    float v;
                    if (j >= SEQ) v = -1e30f;
                    else if (qg < SEQ) v = acc[ni][r] + g_BIAS[(h*SEQ + qg)*SEQ + j];
                    else v = 0.f;
                    Ps[row*LP + perm8(j)] = v;
                }
            }
        }
        __syncthreads();

        // -------- softmax (row reduction; column order irrelevant) --------
        #pragma unroll
        for (int rr=0; rr<8; rr++){
            int row = (tid>>5) + rr*8;
            float* prow = &Ps[row*LP];
            float vals[7];
            float mx = -1e30f;
            #pragma unroll
            for (int i=0;i<7;i++){
                int j = lane + i*32;
                vals[i] = (j < NK) ? prow[j] : -1e30f;
                mx = fmaxf(mx, vals[i]);
            }
            #pragma unroll
            for (int o=16;o>0;o>>=1) mx = fmaxf(mx, __shfl_xor_sync(0xffffffffu, mx, o));
            float s = 0.f;
            #pragma unroll
            for (int i=0;i<7;i++){ vals[i] = __expf(vals[i]-mx); s += vals[i]; }
            #pragma unroll
            for (int o=16;o>0;o>>=1) s += __shfl_xor_sync(0xffffffffu, s, o);
            float inv = 1.f / s;
            #pragma unroll
            for (int i=0;i<7;i++){
                int j = lane + i*32;
                if (j < NK) prow[j] = to_tf32(vals[i]*inv);
            }
        }
        __syncthreads();

        // -------- phase 2: O = P V, warp tile 16 x 32, K = 208 --------
        {
            const int wm = (wid&3)*16, wn = (wid>>2)*32;
            float acc[4][4];
            #pragma unroll
            for (int ni=0;ni<4;ni++)
                #pragma unroll
                for (int r=0;r<4;r++) acc[ni][r]=0.f;
            #pragma unroll
            for (int ks=0; ks<26; ks++){
                const int c2 = ks*8 + 2*lc;        // permuted P columns
                const int cl = ks*8 + lc;          // logical V rows
                int r = wm + lr;
                float2 a0 = *reinterpret_cast<const float2*>(&Ps[r*LP + c2]);
                float2 a1 = *reinterpret_cast<const float2*>(&Ps[(r+8)*LP + c2]);
                uint32_t av[4] = { fbits(a0.x), fbits(a1.x), fbits(a0.y), fbits(a1.y) };
                #pragma unroll
                for (int ni=0;ni<4;ni++){
                    int n = wn + ni*8 + lr;
                    uint32_t bv[2];
                    bv[0] = fbits(Vs[cl*LQ + n]);
                    bv[1] = fbits(Vs[(cl+4)*LQ + n]);
                    mma8(acc[ni], av, bv);
                }
            }
            #pragma unroll
            for (int ni=0;ni<4;ni++){
                #pragma unroll
                for (int r=0;r<4;r++){
                    int row = wm + (r>>1)*8 + lr;
                    int hdc = wn + ni*8 + lc*2 + (r&1);
                    int qg  = qt*64 + row;
                    if (qg < SEQ)
                        g_ATT[((size_t)b*SEQ + qg)*DIMC + h*HD + perm8(hdc)] = to_tf32(acc[ni][r]);
                }
            }
        }
        __syncthreads();   // before next q-tile overwrites Qs/Ps
    }
}

// ---------------- launch ----------------
extern "C" void kernel_launch(void* const* d_in, const int* in_sizes, int n_in,
                              void* d_out, int out_size){
    const float* x      = (const float*)d_in[0];
    const float* qkv_w  = (const float*)d_in[1];
    const float* q_bias = (const float*)d_in[2];
    const float* v_bias = (const float*)d_in[3];
    const float* table  = (const float*)d_in[4];
    const float* proj_w = (const float*)d_in[5];
    const float* proj_b = (const float*)d_in[6];
    const int*   relidx = (const int*)d_in[7];
    float* out = (float*)d_out;

    const int gemm_smem = 4 * TBUF * (int)sizeof(float);                    // 81920
    const int attn_smem = (64*LQ + 2*NK*LQ + 64*LP) * (int)sizeof(float);   // 193536
    cudaFuncSetAttribute(gemm_tf32<0>, cudaFuncAttributeMaxDynamicSharedMemorySize, gemm_smem);
    cudaFuncSetAttribute(gemm_tf32<1>, cudaFuncAttributeMaxDynamicSharedMemorySize, gemm_smem);
    cudaFuncSetAttribute(attn_kernel,  cudaFuncAttributeMaxDynamicSharedMemorySize, attn_smem);

    const int nx8  = (MTOT*DIMC)/8;           // 4,841,472
    const int nw18 = (3*DIMC*DIMC)/8;         // 221,184
    const int nw28 = (DIMC*DIMC)/8;           // 73,728
    round_perm_kernel<0><<<(nx8 +255)/256, 256>>>(x,      nx8);
    round_perm_kernel<1><<<(nw18+255)/256, 256>>>(qkv_w,  nw18);
    round_perm_kernel<2><<<(nw28+255)/256, 256>>>(proj_w, nw28);
    bias_gather_kernel<<<(HEADS*SEQ*SEQ + 255)/256, 256>>>(table, relidx);

    gemm_tf32<0><<<dim3(3*DIMC/128, MTOT/128), 256, gemm_smem>>>(
        q_bias, v_bias, nullptr);

    attn_kernel<<<dim3(HEADS, BATCH), 256, attn_smem>>>();

    gemm_tf32<1><<<dim3(DIMC/128, MTOT/128), 256, gemm_smem>>>(
        proj_b, nullptr, out);
}